// round 6
// baseline (speedup 1.0000x reference)
#include <cuda_runtime.h>
#include <cuda_bf16.h>
#include <cstdint>

#define N_NODES 100000
#define N_EDGES 1600000
#define D 64

// ---------------------------------------------------------------------------
// Kernel 1: zero the accumulator (d_out is poisoned to 0xAA by the harness).
// ---------------------------------------------------------------------------
__global__ void zero_kernel(float4* __restrict__ out, int n4) {
    int i = blockIdx.x * blockDim.x + threadIdx.x;
    int stride = gridDim.x * blockDim.x;
    for (; i < n4; i += stride) out[i] = make_float4(0.f, 0.f, 0.f, 0.f);
}

// ---------------------------------------------------------------------------
// Kernel 2: edge scatter.  16 threads per edge, one float4 chunk each.
// Gather feature[src[e]] (coalesced 256B per edge) and red.global.add.v4.f32
// into accum[dst[e]].  Vectorized RED = 4x fewer atomic lanes vs scalar.
// ---------------------------------------------------------------------------
__global__ void scatter_kernel(const float4* __restrict__ feat4,
                               const int* __restrict__ src,
                               const int* __restrict__ dst,
                               float4* __restrict__ accum4) {
    int t = blockIdx.x * blockDim.x + threadIdx.x;   // 16 threads per edge
    int e = t >> 4;
    int c = t & 15;                                   // float4 chunk within row
    if (e >= N_EDGES) return;
    int s = __ldg(&src[e]);
    int d = __ldg(&dst[e]);
    float4 v = __ldg(&feat4[(size_t)s * 16 + c]);
    float4* p = &accum4[(size_t)d * 16 + c];
    asm volatile("red.global.add.v4.f32 [%0], {%1, %2, %3, %4};"
                 :: "l"(p), "f"(v.x), "f"(v.y), "f"(v.z), "f"(v.w)
                 : "memory");
}

// ---------------------------------------------------------------------------
// Kernel 3: in-place row transform  out[v] = accum[v] @ W^T + b.
// 256 threads = 4 nodes x 64 lanes. W staged transposed in shared
// (Wt[k][j]) so the inner loop is conflict-free; each block reads its 4 rows
// into shared BEFORE overwriting them -> in-place is safe.
// ---------------------------------------------------------------------------
__global__ __launch_bounds__(256)
void gemm_kernel(float* __restrict__ io,          // accum in, result out
                 const float* __restrict__ W,     // [D_OUT, D_IN] row-major
                 const float* __restrict__ b) {
    __shared__ float Wt[D * D];      // Wt[k*64 + j] = W[j*64 + k]
    __shared__ float rows[4][D];
    __shared__ float bs[D];

    int tid = threadIdx.x;
    // stage W transposed
    for (int i = tid; i < D * D; i += 256) {
        int j = i / D, k = i % D;
        Wt[k * D + j] = W[i];
    }
    if (tid < D) bs[tid] = b[tid];

    int g = tid >> 6;        // node group 0..3
    int j = tid & 63;        // output column
    int v = blockIdx.x * 4 + g;

    rows[g][j] = io[(size_t)v * D + j];
    __syncthreads();

    float acc = bs[j];
    const float* r = rows[g];
    #pragma unroll 16
    for (int k = 0; k < D; k++) {
        acc = fmaf(r[k], Wt[k * D + j], acc);
    }
    io[(size_t)v * D + j] = acc;
}

// ---------------------------------------------------------------------------
// launch
// ---------------------------------------------------------------------------
extern "C" void kernel_launch(void* const* d_in, const int* in_sizes, int n_in,
                              void* d_out, int out_size) {
    const float* feature = (const float*)d_in[0];
    const int*   src     = (const int*)d_in[1];
    const int*   dst     = (const int*)d_in[2];
    const float* W       = (const float*)d_in[3];
    const float* b       = (const float*)d_in[4];
    float* out = (float*)d_out;

    int n4 = N_NODES * D / 4;                       // 1.6M float4
    zero_kernel<<<1024, 256>>>((float4*)out, n4);

    int scatter_threads = N_EDGES * 16;             // 25.6M
    scatter_kernel<<<scatter_threads / 256, 256>>>(
        (const float4*)feature, src, dst, (float4*)out);

    gemm_kernel<<<N_NODES / 4, 256>>>(out, W, b);
}

// round 9
// speedup vs baseline: 1.4974x; 1.4974x over previous
#include <cuda_runtime.h>
#include <cuda_bf16.h>
#include <cstdint>

#define N_NODES 100000
#define N_EDGES 1600000
#define D 64

#define SCAN_THREADS 1024
#define SCAN_CHUNK   98          // 1024 * 98 = 100352 >= N_NODES

// ---------------------------------------------------------------------------
// Scratch (static device globals — no allocation).
// ---------------------------------------------------------------------------
__device__ int g_cnt[N_NODES];      // per-dst degree
__device__ int g_off[N_NODES];      // exclusive-scan start offsets
__device__ int g_cursor[N_NODES];   // fill cursor; after fill == off + cnt
__device__ int g_srcidx[N_EDGES];   // src node ids, grouped by dst

// ---------------------------------------------------------------------------
// Kernel 1: zero the histogram counters.
// ---------------------------------------------------------------------------
__global__ void zero_cnt_kernel() {
    int i = blockIdx.x * blockDim.x + threadIdx.x;
    if (i < N_NODES) g_cnt[i] = 0;
}

// ---------------------------------------------------------------------------
// Kernel 2: histogram of dst.
// ---------------------------------------------------------------------------
__global__ void hist_kernel(const int* __restrict__ dst) {
    int e = blockIdx.x * blockDim.x + threadIdx.x;
    if (e < N_EDGES) atomicAdd(&g_cnt[__ldg(&dst[e])], 1);
}

// ---------------------------------------------------------------------------
// Kernel 3: exclusive scan of g_cnt -> g_off, g_cursor. Single block.
// Two passes over global; Hillis-Steele block scan of per-thread chunk sums.
// ---------------------------------------------------------------------------
__global__ __launch_bounds__(SCAN_THREADS)
void scan_kernel() {
    __shared__ int sums[SCAN_THREADS];
    int t = threadIdx.x;
    int base = t * SCAN_CHUNK;

    // pass 1: per-thread chunk total
    int s = 0;
    #pragma unroll 7
    for (int i = 0; i < SCAN_CHUNK; i++) {
        int idx = base + i;
        if (idx < N_NODES) s += g_cnt[idx];
    }
    sums[t] = s;
    __syncthreads();

    // inclusive block scan
    for (int off = 1; off < SCAN_THREADS; off <<= 1) {
        int v = (t >= off) ? sums[t - off] : 0;
        __syncthreads();
        sums[t] += v;
        __syncthreads();
    }

    // pass 2: write exclusive offsets for this chunk
    int run = sums[t] - s;
    for (int i = 0; i < SCAN_CHUNK; i++) {
        int idx = base + i;
        if (idx < N_NODES) {
            int c = g_cnt[idx];
            g_off[idx] = run;
            g_cursor[idx] = run;
            run += c;
        }
    }
}

// ---------------------------------------------------------------------------
// Kernel 4: scatter src ids into dst-grouped order.
// ---------------------------------------------------------------------------
__global__ void fill_kernel(const int* __restrict__ src,
                            const int* __restrict__ dst) {
    int e = blockIdx.x * blockDim.x + threadIdx.x;
    if (e < N_EDGES) {
        int d = __ldg(&dst[e]);
        int pos = atomicAdd(&g_cursor[d], 1);
        g_srcidx[pos] = __ldg(&src[e]);
    }
}

// ---------------------------------------------------------------------------
// Kernel 5: fused segmented gather-sum + linear.
// 256 threads = 4 nodes x 64 lanes. Persistent grid: W^T staged in shared
// once per block. For node v, the 64 lanes walk its contiguous edge segment,
// each lane accumulating one feature column (coalesced 256B row reads, all
// L2-resident). Then out[v] = h[v] @ W^T + b via shared row + Wt.
// No floating-point atomics anywhere.
// ---------------------------------------------------------------------------
__global__ __launch_bounds__(256)
void gather_gemm_kernel(const float* __restrict__ feat,
                        const float* __restrict__ W,
                        const float* __restrict__ b,
                        float* __restrict__ out) {
    __shared__ float Wt[D * D];      // Wt[k*64 + j] = W[j*64 + k]
    __shared__ float rows[4][D];
    __shared__ float bs[D];

    int tid = threadIdx.x;
    for (int i = tid; i < D * D; i += 256) {
        int j = i / D, k = i % D;
        Wt[k * D + j] = __ldg(&W[i]);
    }
    if (tid < D) bs[tid] = __ldg(&b[tid]);
    __syncthreads();

    int g = tid >> 6;                // node slot 0..3
    int j = tid & 63;                // feature / output column

    for (int v0 = blockIdx.x * 4; v0 < N_NODES; v0 += gridDim.x * 4) {
        int v = v0 + g;
        float acc = 0.f;
        if (v < N_NODES) {
            int i   = g_off[v];
            int end = g_cursor[v];   // == off + cnt after fill
            for (; i < end; i++) {
                int s = __ldg(&g_srcidx[i]);             // broadcast across 64 lanes
                acc += __ldg(&feat[(size_t)s * D + j]);  // coalesced 256B row
            }
        }
        rows[g][j] = acc;
        __syncthreads();

        if (v < N_NODES) {
            float o = bs[j];
            const float* r = rows[g];
            #pragma unroll
            for (int k = 0; k < D; k++)
                o = fmaf(r[k], Wt[k * D + j], o);
            out[(size_t)v * D + j] = o;
        }
        __syncthreads();             // before rows[] is overwritten
    }
}

// ---------------------------------------------------------------------------
// launch
// ---------------------------------------------------------------------------
extern "C" void kernel_launch(void* const* d_in, const int* in_sizes, int n_in,
                              void* d_out, int out_size) {
    const float* feature = (const float*)d_in[0];
    const int*   src     = (const int*)d_in[1];
    const int*   dst     = (const int*)d_in[2];
    const float* W       = (const float*)d_in[3];
    const float* b       = (const float*)d_in[4];
    float* out = (float*)d_out;

    zero_cnt_kernel<<<(N_NODES + 255) / 256, 256>>>();
    hist_kernel<<<(N_EDGES + 255) / 256, 256>>>(dst);
    scan_kernel<<<1, SCAN_THREADS>>>();
    fill_kernel<<<(N_EDGES + 255) / 256, 256>>>(src, dst);

    // persistent grid: ~8 blocks/SM * 148 SMs (thread-limited: 2048/256 = 8)
    gather_gemm_kernel<<<1184, 256>>>(feature, W, b, out);
}

// round 14
// speedup vs baseline: 1.7308x; 1.1558x over previous
#include <cuda_runtime.h>
#include <cuda_bf16.h>
#include <cstdint>

#define N_NODES 100000
#define N_EDGES 1600000
#define D 64

#define SCAN_THREADS 1024
#define SCAN_CHUNK   98          // 1024 * 98 = 100352 >= N_NODES

// ---------------------------------------------------------------------------
// Scratch (static device globals — no allocation).
// ---------------------------------------------------------------------------
__device__ int g_cnt[N_NODES];      // per-dst degree
__device__ int g_off[N_NODES];      // exclusive-scan start offsets
__device__ int g_cursor[N_NODES];   // fill cursor; after fill == off + cnt
__device__ int g_srcidx[N_EDGES];   // src node ids, grouped by dst

// ---------------------------------------------------------------------------
// Kernel 1: zero the histogram counters.
// ---------------------------------------------------------------------------
__global__ void zero_cnt_kernel() {
    int i = blockIdx.x * blockDim.x + threadIdx.x;
    if (i < N_NODES) g_cnt[i] = 0;
}

// ---------------------------------------------------------------------------
// Kernel 2: histogram of dst (4 edges per thread, int4 loads).
// ---------------------------------------------------------------------------
__global__ void hist_kernel(const int4* __restrict__ dst4) {
    int e = blockIdx.x * blockDim.x + threadIdx.x;
    if (e < N_EDGES / 4) {
        int4 d = __ldg(&dst4[e]);
        atomicAdd(&g_cnt[d.x], 1);
        atomicAdd(&g_cnt[d.y], 1);
        atomicAdd(&g_cnt[d.z], 1);
        atomicAdd(&g_cnt[d.w], 1);
    }
}

// ---------------------------------------------------------------------------
// Kernel 3: exclusive scan of g_cnt -> g_off, g_cursor. Single block.
// ---------------------------------------------------------------------------
__global__ __launch_bounds__(SCAN_THREADS)
void scan_kernel() {
    __shared__ int sums[SCAN_THREADS];
    int t = threadIdx.x;
    int base = t * SCAN_CHUNK;

    int s = 0;
    #pragma unroll 7
    for (int i = 0; i < SCAN_CHUNK; i++) {
        int idx = base + i;
        if (idx < N_NODES) s += g_cnt[idx];
    }
    sums[t] = s;
    __syncthreads();

    for (int off = 1; off < SCAN_THREADS; off <<= 1) {
        int v = (t >= off) ? sums[t - off] : 0;
        __syncthreads();
        sums[t] += v;
        __syncthreads();
    }

    int run = sums[t] - s;
    for (int i = 0; i < SCAN_CHUNK; i++) {
        int idx = base + i;
        if (idx < N_NODES) {
            int c = g_cnt[idx];
            g_off[idx] = run;
            g_cursor[idx] = run;
            run += c;
        }
    }
}

// ---------------------------------------------------------------------------
// Kernel 4: scatter src ids into dst-grouped order (4 edges per thread).
// ---------------------------------------------------------------------------
__global__ void fill_kernel(const int4* __restrict__ src4,
                            const int4* __restrict__ dst4) {
    int e = blockIdx.x * blockDim.x + threadIdx.x;
    if (e < N_EDGES / 4) {
        int4 d = __ldg(&dst4[e]);
        int4 s = __ldg(&src4[e]);
        g_srcidx[atomicAdd(&g_cursor[d.x], 1)] = s.x;
        g_srcidx[atomicAdd(&g_cursor[d.y], 1)] = s.y;
        g_srcidx[atomicAdd(&g_cursor[d.z], 1)] = s.z;
        g_srcidx[atomicAdd(&g_cursor[d.w], 1)] = s.w;
    }
}

// ---------------------------------------------------------------------------
// Kernel 5: fused segmented gather-sum + linear.  WARP-PER-NODE.
// 32 lanes x float2 = one 64-float feature row per warp. Segment walk
// manually unrolled x4 with independent accumulators (MLP>=4). No block
// syncs in the main loop -> no degree-skew coupling between warps.
// GEMM: row staged in warp-private shared; Wt2[k][l] = (W[2l][k], W[2l+1][k])
// so each lane produces outputs 2l, 2l+1 via broadcast h[k] + vector LDS.
// ---------------------------------------------------------------------------
__global__ __launch_bounds__(256)
void gather_gemm_kernel(const float2* __restrict__ feat2,
                        const float* __restrict__ W,
                        const float* __restrict__ b,
                        float2* __restrict__ out2) {
    __shared__ float2 Wt2[D * 32];       // 16 KB
    __shared__ float  rows[8][D];        // 2 KB, one row per warp
    __shared__ float2 bs2[32];

    int tid = threadIdx.x;
    for (int i = tid; i < D * 32; i += 256) {
        int k = i >> 5, l = i & 31;
        Wt2[i] = make_float2(__ldg(&W[(2 * l) * D + k]),
                             __ldg(&W[(2 * l + 1) * D + k]));
    }
    if (tid < 32) bs2[tid] = make_float2(__ldg(&b[2 * tid]),
                                         __ldg(&b[2 * tid + 1]));
    __syncthreads();

    int w = tid >> 5;
    int l = tid & 31;
    float* myrow = rows[w];
    int warp_global = blockIdx.x * 8 + w;
    int nwarps = gridDim.x * 8;

    for (int v = warp_global; v < N_NODES; v += nwarps) {
        int i   = g_off[v];
        int end = g_cursor[v];

        float2 a0 = {0.f, 0.f}, a1 = {0.f, 0.f};
        float2 a2 = {0.f, 0.f}, a3 = {0.f, 0.f};

        for (; i + 4 <= end; i += 4) {
            int s0 = __ldg(&g_srcidx[i]);
            int s1 = __ldg(&g_srcidx[i + 1]);
            int s2 = __ldg(&g_srcidx[i + 2]);
            int s3 = __ldg(&g_srcidx[i + 3]);
            float2 f0 = __ldg(&feat2[(size_t)s0 * 32 + l]);
            float2 f1 = __ldg(&feat2[(size_t)s1 * 32 + l]);
            float2 f2 = __ldg(&feat2[(size_t)s2 * 32 + l]);
            float2 f3 = __ldg(&feat2[(size_t)s3 * 32 + l]);
            a0.x += f0.x; a0.y += f0.y;
            a1.x += f1.x; a1.y += f1.y;
            a2.x += f2.x; a2.y += f2.y;
            a3.x += f3.x; a3.y += f3.y;
        }
        for (; i < end; i++) {
            int s = __ldg(&g_srcidx[i]);
            float2 f = __ldg(&feat2[(size_t)s * 32 + l]);
            a0.x += f.x; a0.y += f.y;
        }
        float2 acc = make_float2((a0.x + a1.x) + (a2.x + a3.x),
                                 (a0.y + a1.y) + (a2.y + a3.y));

        ((float2*)myrow)[l] = acc;
        __syncwarp();

        float2 o = bs2[l];
        #pragma unroll
        for (int k = 0; k < D; k++) {
            float  hk = myrow[k];           // broadcast LDS
            float2 wv = Wt2[k * 32 + l];
            o.x = fmaf(hk, wv.x, o.x);
            o.y = fmaf(hk, wv.y, o.y);
        }
        out2[(size_t)v * 32 + l] = o;
        __syncwarp();                        // before myrow is overwritten
    }
}

// ---------------------------------------------------------------------------
// launch
// ---------------------------------------------------------------------------
extern "C" void kernel_launch(void* const* d_in, const int* in_sizes, int n_in,
                              void* d_out, int out_size) {
    const float* feature = (const float*)d_in[0];
    const int*   src     = (const int*)d_in[1];
    const int*   dst     = (const int*)d_in[2];
    const float* W       = (const float*)d_in[3];
    const float* b       = (const float*)d_in[4];
    float* out = (float*)d_out;

    zero_cnt_kernel<<<(N_NODES + 255) / 256, 256>>>();
    hist_kernel<<<(N_EDGES / 4 + 255) / 256, 256>>>((const int4*)dst);
    scan_kernel<<<1, SCAN_THREADS>>>();
    fill_kernel<<<(N_EDGES / 4 + 255) / 256, 256>>>((const int4*)src,
                                                    (const int4*)dst);

    // persistent: 8 blocks/SM x 148 SMs
    gather_gemm_kernel<<<1184, 256>>>((const float2*)feature, W, b,
                                      (float2*)out);
}

// round 15
// speedup vs baseline: 1.7334x; 1.0015x over previous
#include <cuda_runtime.h>
#include <cuda_bf16.h>
#include <cstdint>

#define N_NODES 100000
#define N_EDGES 1600000
#define D 64

#define SCAN_THREADS 1024
#define SCAN_CHUNK   98          // 1024 * 98 = 100352 >= N_NODES

// ---------------------------------------------------------------------------
// Scratch (static device globals — no allocation).
// ---------------------------------------------------------------------------
__device__ int g_cnt[N_NODES];      // per-dst degree
__device__ int g_off[N_NODES];      // exclusive-scan start offsets
__device__ int g_cursor[N_NODES];   // fill cursor; after fill == off + cnt
__device__ int g_srcidx[N_EDGES];   // src node ids, grouped by dst

// ---------------------------------------------------------------------------
// Kernel 1: zero the histogram counters.
// ---------------------------------------------------------------------------
__global__ void zero_cnt_kernel() {
    int i = blockIdx.x * blockDim.x + threadIdx.x;
    if (i < N_NODES) g_cnt[i] = 0;
}

// ---------------------------------------------------------------------------
// Kernel 2: histogram of dst (4 edges per thread, int4 loads).
// ---------------------------------------------------------------------------
__global__ void hist_kernel(const int4* __restrict__ dst4) {
    int e = blockIdx.x * blockDim.x + threadIdx.x;
    if (e < N_EDGES / 4) {
        int4 d = __ldg(&dst4[e]);
        atomicAdd(&g_cnt[d.x], 1);
        atomicAdd(&g_cnt[d.y], 1);
        atomicAdd(&g_cnt[d.z], 1);
        atomicAdd(&g_cnt[d.w], 1);
    }
}

// ---------------------------------------------------------------------------
// Kernel 3: exclusive scan of g_cnt -> g_off, g_cursor. Single block.
// ---------------------------------------------------------------------------
__global__ __launch_bounds__(SCAN_THREADS)
void scan_kernel() {
    __shared__ int sums[SCAN_THREADS];
    int t = threadIdx.x;
    int base = t * SCAN_CHUNK;

    int s = 0;
    #pragma unroll 7
    for (int i = 0; i < SCAN_CHUNK; i++) {
        int idx = base + i;
        if (idx < N_NODES) s += g_cnt[idx];
    }
    sums[t] = s;
    __syncthreads();

    for (int off = 1; off < SCAN_THREADS; off <<= 1) {
        int v = (t >= off) ? sums[t - off] : 0;
        __syncthreads();
        sums[t] += v;
        __syncthreads();
    }

    int run = sums[t] - s;
    for (int i = 0; i < SCAN_CHUNK; i++) {
        int idx = base + i;
        if (idx < N_NODES) {
            int c = g_cnt[idx];
            g_off[idx] = run;
            g_cursor[idx] = run;
            run += c;
        }
    }
}

// ---------------------------------------------------------------------------
// Kernel 4: scatter src ids into dst-grouped order (4 edges per thread).
// ---------------------------------------------------------------------------
__global__ void fill_kernel(const int4* __restrict__ src4,
                            const int4* __restrict__ dst4) {
    int e = blockIdx.x * blockDim.x + threadIdx.x;
    if (e < N_EDGES / 4) {
        int4 d = __ldg(&dst4[e]);
        int4 s = __ldg(&src4[e]);
        g_srcidx[atomicAdd(&g_cursor[d.x], 1)] = s.x;
        g_srcidx[atomicAdd(&g_cursor[d.y], 1)] = s.y;
        g_srcidx[atomicAdd(&g_cursor[d.z], 1)] = s.z;
        g_srcidx[atomicAdd(&g_cursor[d.w], 1)] = s.w;
    }
}

// ---------------------------------------------------------------------------
// Kernel 5: fused segmented gather-sum + linear.  WARP-PER-NODE with
// cooperative index staging:
//   * ONE coalesced LDG pulls up to 32 segment indices into the warp's lanes;
//     indices are then broadcast via SHFL (no dependent index loads in the
//     inner loop) -> every feature load in the segment issues back-to-back.
//   * 16 lanes x float4 cover a 256B row; warp halves process even/odd edges
//     (2 edges per step), unrolled x4 -> 8 LDG.128 in flight.
//   * Cross-half combine via 4x SHFL.XOR(16), then shared-staged W^T GEMM.
// ---------------------------------------------------------------------------
__global__ __launch_bounds__(256)
void gather_gemm_kernel(const float4* __restrict__ feat4,
                        const float* __restrict__ W,
                        const float* __restrict__ b,
                        float2* __restrict__ out2) {
    __shared__ float2 Wt2[D * 32];       // 16 KB: Wt2[k*32+l] = (W[2l][k], W[2l+1][k])
    __shared__ float  rows[8][D];        // one row per warp
    __shared__ float2 bs2[32];

    int tid = threadIdx.x;
    for (int i = tid; i < D * 32; i += 256) {
        int k = i >> 5, l = i & 31;
        Wt2[i] = make_float2(__ldg(&W[(2 * l) * D + k]),
                             __ldg(&W[(2 * l + 1) * D + k]));
    }
    if (tid < 32) bs2[tid] = make_float2(__ldg(&b[2 * tid]),
                                         __ldg(&b[2 * tid + 1]));
    __syncthreads();

    const int w    = tid >> 5;
    const int lane = tid & 31;
    const int half = lane >> 4;          // 0: even edges, 1: odd edges
    const int q    = lane & 15;          // float4 quad within the row
    float* myrow = rows[w];

    int warp_global = blockIdx.x * 8 + w;
    int nwarps = gridDim.x * 8;

    for (int v = warp_global; v < N_NODES; v += nwarps) {
        int off  = g_off[v];
        int nseg = g_cursor[v] - off;

        float4 acc = make_float4(0.f, 0.f, 0.f, 0.f);

        for (int base = 0; base < nseg; base += 32) {
            int rem = nseg - base;
            if (rem > 32) rem = 32;
            // one coalesced load of up to 32 indices into the warp's lanes
            int myidx = __ldg(&g_srcidx[off + base + ((lane < rem) ? lane : 0)]);

            int j = 0;
            for (; j + 8 <= rem; j += 8) {
                int s0 = __shfl_sync(0xffffffffu, myidx, j + 0 + half);
                int s1 = __shfl_sync(0xffffffffu, myidx, j + 2 + half);
                int s2 = __shfl_sync(0xffffffffu, myidx, j + 4 + half);
                int s3 = __shfl_sync(0xffffffffu, myidx, j + 6 + half);
                float4 f0 = __ldg(&feat4[(size_t)s0 * 16 + q]);
                float4 f1 = __ldg(&feat4[(size_t)s1 * 16 + q]);
                float4 f2 = __ldg(&feat4[(size_t)s2 * 16 + q]);
                float4 f3 = __ldg(&feat4[(size_t)s3 * 16 + q]);
                acc.x += f0.x; acc.y += f0.y; acc.z += f0.z; acc.w += f0.w;
                acc.x += f1.x; acc.y += f1.y; acc.z += f1.z; acc.w += f1.w;
                acc.x += f2.x; acc.y += f2.y; acc.z += f2.z; acc.w += f2.w;
                acc.x += f3.x; acc.y += f3.y; acc.z += f3.z; acc.w += f3.w;
            }
            for (; j < rem; j += 2) {
                int jj = j + half;
                int sl = (jj < rem) ? jj : j;          // clamp to a valid lane
                int s  = __shfl_sync(0xffffffffu, myidx, sl);
                float4 f = __ldg(&feat4[(size_t)s * 16 + q]);
                if (jj < rem) {
                    acc.x += f.x; acc.y += f.y; acc.z += f.z; acc.w += f.w;
                }
            }
        }

        // combine even-edge and odd-edge halves (lanes l <-> l+16)
        acc.x += __shfl_xor_sync(0xffffffffu, acc.x, 16);
        acc.y += __shfl_xor_sync(0xffffffffu, acc.y, 16);
        acc.z += __shfl_xor_sync(0xffffffffu, acc.z, 16);
        acc.w += __shfl_xor_sync(0xffffffffu, acc.w, 16);

        if (half == 0) ((float4*)myrow)[q] = acc;
        __syncwarp();

        // out[v] = myrow @ W^T + b : each lane produces columns 2l, 2l+1
        float2 o = bs2[lane];
        #pragma unroll
        for (int k = 0; k < D; k++) {
            float  hk = myrow[k];            // broadcast LDS
            float2 wv = Wt2[k * 32 + lane];
            o.x = fmaf(hk, wv.x, o.x);
            o.y = fmaf(hk, wv.y, o.y);
        }
        out2[(size_t)v * 32 + lane] = o;
        __syncwarp();                        // before myrow is overwritten
    }
}

// ---------------------------------------------------------------------------
// launch
// ---------------------------------------------------------------------------
extern "C" void kernel_launch(void* const* d_in, const int* in_sizes, int n_in,
                              void* d_out, int out_size) {
    const float* feature = (const float*)d_in[0];
    const int*   src     = (const int*)d_in[1];
    const int*   dst     = (const int*)d_in[2];
    const float* W       = (const float*)d_in[3];
    const float* b       = (const float*)d_in[4];
    float* out = (float*)d_out;

    zero_cnt_kernel<<<(N_NODES + 255) / 256, 256>>>();
    hist_kernel<<<(N_EDGES / 4 + 255) / 256, 256>>>((const int4*)dst);
    scan_kernel<<<1, SCAN_THREADS>>>();
    fill_kernel<<<(N_EDGES / 4 + 255) / 256, 256>>>((const int4*)src,
                                                    (const int4*)dst);

    // persistent: 8 blocks/SM x 148 SMs
    gather_gemm_kernel<<<1184, 256>>>((const float4*)feature, W, b,
                                      (float2*)out);
}

// round 17
// speedup vs baseline: 1.9043x; 1.0986x over previous
#include <cuda_runtime.h>
#include <cuda_bf16.h>
#include <cstdint>

#define N_NODES 100000
#define N_EDGES 1600000
#define D 64

#define SCAN_THREADS 1024
#define SCAN_CHUNK   98          // 1024 * 98 = 100352 >= N_NODES

// ---------------------------------------------------------------------------
// Scratch (static device globals — no allocation). g_cnt is zero-initialized
// at module load; gemm_kernel re-zeroes it at the end of every replay, so
// every kernel_launch sequence starts AND ends with g_cnt == 0.
// ---------------------------------------------------------------------------
__device__ int g_cnt[N_NODES];      // per-dst degree (zeroed at start of replay)
__device__ int g_off[N_NODES];      // exclusive-scan start offsets
__device__ int g_cursor[N_NODES];   // fill cursor; after fill == off + cnt
__device__ int g_srcidx[N_EDGES];   // src node ids, grouped by dst

// ---------------------------------------------------------------------------
// Kernel 1: histogram of dst (4 edges per thread, int4 loads).
// ---------------------------------------------------------------------------
__global__ void hist_kernel(const int4* __restrict__ dst4) {
    int e = blockIdx.x * blockDim.x + threadIdx.x;
    if (e < N_EDGES / 4) {
        int4 d = __ldg(&dst4[e]);
        atomicAdd(&g_cnt[d.x], 1);
        atomicAdd(&g_cnt[d.y], 1);
        atomicAdd(&g_cnt[d.z], 1);
        atomicAdd(&g_cnt[d.w], 1);
    }
}

// ---------------------------------------------------------------------------
// Kernel 2: exclusive scan of g_cnt -> g_off, g_cursor. Single block.
// ---------------------------------------------------------------------------
__global__ __launch_bounds__(SCAN_THREADS)
void scan_kernel() {
    __shared__ int sums[SCAN_THREADS];
    int t = threadIdx.x;
    int base = t * SCAN_CHUNK;

    int s = 0;
    #pragma unroll 7
    for (int i = 0; i < SCAN_CHUNK; i++) {
        int idx = base + i;
        if (idx < N_NODES) s += g_cnt[idx];
    }
    sums[t] = s;
    __syncthreads();

    for (int off = 1; off < SCAN_THREADS; off <<= 1) {
        int v = (t >= off) ? sums[t - off] : 0;
        __syncthreads();
        sums[t] += v;
        __syncthreads();
    }

    int run = sums[t] - s;
    for (int i = 0; i < SCAN_CHUNK; i++) {
        int idx = base + i;
        if (idx < N_NODES) {
            int c = g_cnt[idx];
            g_off[idx] = run;
            g_cursor[idx] = run;
            run += c;
        }
    }
}

// ---------------------------------------------------------------------------
// Kernel 3: scatter src ids into dst-grouped order (4 edges per thread).
// ---------------------------------------------------------------------------
__global__ void fill_kernel(const int4* __restrict__ src4,
                            const int4* __restrict__ dst4) {
    int e = blockIdx.x * blockDim.x + threadIdx.x;
    if (e < N_EDGES / 4) {
        int4 d = __ldg(&dst4[e]);
        int4 s = __ldg(&src4[e]);
        g_srcidx[atomicAdd(&g_cursor[d.x], 1)] = s.x;
        g_srcidx[atomicAdd(&g_cursor[d.y], 1)] = s.y;
        g_srcidx[atomicAdd(&g_cursor[d.z], 1)] = s.z;
        g_srcidx[atomicAdd(&g_cursor[d.w], 1)] = s.w;
    }
}

// ---------------------------------------------------------------------------
// Kernel 4 (4th launch -> ncu-profiled): PURE segmented gather-sum.
// Warp-per-node. One coalesced LDG stages up to 32 segment indices into the
// warp's lanes; SHFL distributes them (no dependent index loads). 16 lanes x
// float4 cover a 256B row; warp halves process even/odd edges; unroll x4
// (8 edges, 4 independent LDG.128 + 4 independent accumulators). Writes h
// rows directly to d_out. No shared memory, no block syncs.
// ---------------------------------------------------------------------------
__global__ __launch_bounds__(256)
void gather_kernel(const float4* __restrict__ feat4,
                   float4* __restrict__ out4) {
    const int lane = threadIdx.x & 31;
    const int w    = threadIdx.x >> 5;
    const int half = lane >> 4;          // 0: even edges, 1: odd edges
    const int q    = lane & 15;          // float4 quad within the row

    int v = blockIdx.x * 8 + w;
    if (v >= N_NODES) return;

    int off  = g_off[v];
    int nseg = g_cursor[v] - off;

    float4 a0 = {0.f,0.f,0.f,0.f}, a1 = {0.f,0.f,0.f,0.f};
    float4 a2 = {0.f,0.f,0.f,0.f}, a3 = {0.f,0.f,0.f,0.f};

    for (int base = 0; base < nseg; base += 32) {
        int rem = nseg - base;
        if (rem > 32) rem = 32;
        int myidx = __ldg(&g_srcidx[off + base + ((lane < rem) ? lane : 0)]);

        int j = 0;
        for (; j + 8 <= rem; j += 8) {
            int s0 = __shfl_sync(0xffffffffu, myidx, j + 0 + half);
            int s1 = __shfl_sync(0xffffffffu, myidx, j + 2 + half);
            int s2 = __shfl_sync(0xffffffffu, myidx, j + 4 + half);
            int s3 = __shfl_sync(0xffffffffu, myidx, j + 6 + half);
            float4 f0 = __ldg(&feat4[(size_t)s0 * 16 + q]);
            float4 f1 = __ldg(&feat4[(size_t)s1 * 16 + q]);
            float4 f2 = __ldg(&feat4[(size_t)s2 * 16 + q]);
            float4 f3 = __ldg(&feat4[(size_t)s3 * 16 + q]);
            a0.x += f0.x; a0.y += f0.y; a0.z += f0.z; a0.w += f0.w;
            a1.x += f1.x; a1.y += f1.y; a1.z += f1.z; a1.w += f1.w;
            a2.x += f2.x; a2.y += f2.y; a2.z += f2.z; a2.w += f2.w;
            a3.x += f3.x; a3.y += f3.y; a3.z += f3.z; a3.w += f3.w;
        }
        for (; j < rem; j += 2) {
            int jj = j + half;
            int sl = (jj < rem) ? jj : j;
            int s  = __shfl_sync(0xffffffffu, myidx, sl);
            float4 f = __ldg(&feat4[(size_t)s * 16 + q]);
            if (jj < rem) {
                a0.x += f.x; a0.y += f.y; a0.z += f.z; a0.w += f.w;
            }
        }
    }

    float4 acc = make_float4((a0.x + a1.x) + (a2.x + a3.x),
                             (a0.y + a1.y) + (a2.y + a3.y),
                             (a0.z + a1.z) + (a2.z + a3.z),
                             (a0.w + a1.w) + (a2.w + a3.w));

    // combine even/odd halves (lane l <-> l+16)
    acc.x += __shfl_xor_sync(0xffffffffu, acc.x, 16);
    acc.y += __shfl_xor_sync(0xffffffffu, acc.y, 16);
    acc.z += __shfl_xor_sync(0xffffffffu, acc.z, 16);
    acc.w += __shfl_xor_sync(0xffffffffu, acc.w, 16);

    if (half == 0) out4[(size_t)v * 16 + q] = acc;
}

// ---------------------------------------------------------------------------
// Kernel 5: tiled in-place GEMM  out[v] = h[v] @ W^T + b.
// Block = 256 threads, tile = 64 nodes x 64 cols. H-tile and W staged in
// shared TRANSPOSED (HT[k][n], WT[k][j], row pitch 68 floats so float4 rows
// stay 16B-aligned). Thread (ty,tx) computes a 4x4 micro-tile: per k-step
// one broadcast LDS.128 (a) + one spread LDS.128 (b) + 16 FFMA.
// Reads its 64 rows into smem BEFORE overwriting -> in-place safe.
// Also re-zeroes g_cnt for the next replay.
// ---------------------------------------------------------------------------
#define GPITCH 68
__global__ __launch_bounds__(256)
void gemm_kernel(float* __restrict__ io,
                 const float* __restrict__ W,
                 const float* __restrict__ b) {
    __shared__ float HT[D][GPITCH];   // HT[k][n_local]
    __shared__ float WT[D][GPITCH];   // WT[k][j]

    int tid = threadIdx.x;
    int n0 = blockIdx.x * 64;

    // re-zero g_cnt (for the next replay; independent of the GEMM)
    int zi = blockIdx.x * 256 + tid;
    if (zi < N_NODES) g_cnt[zi] = 0;

    // stage H tile transposed: thread loads float4 of h, scatters 4 scalars
    #pragma unroll
    for (int r = 0; r < 4; r++) {
        int idx = r * 256 + tid;        // 0..1023 float4 slots
        int nl  = idx >> 4;             // local node 0..63
        int c4  = idx & 15;             // float4 chunk 0..15
        int n   = n0 + nl;
        float4 hv = (n < N_NODES) ? __ldg((const float4*)io + (size_t)n * 16 + c4)
                                  : make_float4(0.f, 0.f, 0.f, 0.f);
        HT[4 * c4 + 0][nl] = hv.x;
        HT[4 * c4 + 1][nl] = hv.y;
        HT[4 * c4 + 2][nl] = hv.z;
        HT[4 * c4 + 3][nl] = hv.w;
    }
    // stage W transposed: W[j][k] -> WT[k][j]
    #pragma unroll
    for (int r = 0; r < 4; r++) {
        int idx = r * 256 + tid;
        int j   = idx >> 4;
        int k4  = idx & 15;
        float4 wv = __ldg((const float4*)W + (size_t)j * 16 + k4);
        WT[4 * k4 + 0][j] = wv.x;
        WT[4 * k4 + 1][j] = wv.y;
        WT[4 * k4 + 2][j] = wv.z;
        WT[4 * k4 + 3][j] = wv.w;
    }
    __syncthreads();

    int tx = tid & 15;                  // col group: cols 4tx..4tx+3
    int ty = tid >> 4;                  // node group: nodes 4ty..4ty+3

    float4 bias = __ldg((const float4*)b + tx);
    float4 c0 = bias, c1 = bias, c2 = bias, c3 = bias;

    #pragma unroll
    for (int k = 0; k < D; k++) {
        float4 a = *(const float4*)&HT[k][4 * ty];   // broadcast across tx
        float4 wv = *(const float4*)&WT[k][4 * tx];  // spread across tx
        c0.x = fmaf(a.x, wv.x, c0.x); c0.y = fmaf(a.x, wv.y, c0.y);
        c0.z = fmaf(a.x, wv.z, c0.z); c0.w = fmaf(a.x, wv.w, c0.w);
        c1.x = fmaf(a.y, wv.x, c1.x); c1.y = fmaf(a.y, wv.y, c1.y);
        c1.z = fmaf(a.y, wv.z, c1.z); c1.w = fmaf(a.y, wv.w, c1.w);
        c2.x = fmaf(a.z, wv.x, c2.x); c2.y = fmaf(a.z, wv.y, c2.y);
        c2.z = fmaf(a.z, wv.z, c2.z); c2.w = fmaf(a.z, wv.w, c2.w);
        c3.x = fmaf(a.w, wv.x, c3.x); c3.y = fmaf(a.w, wv.y, c3.y);
        c3.z = fmaf(a.w, wv.z, c3.z); c3.w = fmaf(a.w, wv.w, c3.w);
    }

    float4* out4 = (float4*)io;
    int nb = n0 + 4 * ty;
    if (nb + 0 < N_NODES) out4[(size_t)(nb + 0) * 16 + tx] = c0;
    if (nb + 1 < N_NODES) out4[(size_t)(nb + 1) * 16 + tx] = c1;
    if (nb + 2 < N_NODES) out4[(size_t)(nb + 2) * 16 + tx] = c2;
    if (nb + 3 < N_NODES) out4[(size_t)(nb + 3) * 16 + tx] = c3;
}

// ---------------------------------------------------------------------------
// launch: hist(1), scan(2), fill(3), gather(4) <- ncu slot, gemm(5)
// ---------------------------------------------------------------------------
extern "C" void kernel_launch(void* const* d_in, const int* in_sizes, int n_in,
                              void* d_out, int out_size) {
    const float* feature = (const float*)d_in[0];
    const int*   src     = (const int*)d_in[1];
    const int*   dst     = (const int*)d_in[2];
    const float* W       = (const float*)d_in[3];
    const float* b       = (const float*)d_in[4];
    float* out = (float*)d_out;

    hist_kernel<<<(N_EDGES / 4 + 255) / 256, 256>>>((const int4*)dst);
    scan_kernel<<<1, SCAN_THREADS>>>();
    fill_kernel<<<(N_EDGES / 4 + 255) / 256, 256>>>((const int4*)src,
                                                    (const int4*)dst);
    gather_kernel<<<(N_NODES + 7) / 8, 256>>>((const float4*)feature,
                                              (float4*)out);
    gemm_kernel<<<(N_NODES + 63) / 64, 256>>>(out, W, b);
}